// round 1
// baseline (speedup 1.0000x reference)
#include <cuda_runtime.h>

// ============================================================================
// 3-layer LSTM (H=32, T=64) over 65536 independent sequences + FC(32->1).
// Thread-per-sequence, weights broadcast from SMEM, packed f32x2 FMA matvec.
// Layer-by-layer with h-sequence staged in __device__ scratch.
// ============================================================================

#define HID 32
#define TT 64
#define NSEQ 65536

typedef unsigned long long ull;

// scratch: [t][seq][32] floats, 512 MB each (uninitialized .bss, no alloc)
__device__ float g_bufA[(size_t)NSEQ * TT * HID];
__device__ float g_bufB[(size_t)NSEQ * TT * HID];

// ---------------- packed f32x2 helpers ----------------
__device__ __forceinline__ ull ffma2(ull a, ull b, ull c) {
    ull d;
    asm("fma.rn.f32x2 %0, %1, %2, %3;" : "=l"(d) : "l"(a), "l"(b), "l"(c));
    return d;
}
__device__ __forceinline__ ull pack2(float lo, float hi) {
    ull r;
    asm("mov.b64 %0, {%1, %2};" : "=l"(r) : "f"(lo), "f"(hi));
    return r;
}
__device__ __forceinline__ void unpack2(ull v, float& lo, float& hi) {
    asm("mov.b64 {%0, %1}, %2;" : "=f"(lo), "=f"(hi) : "l"(v));
}

// ---------------- fast activations ----------------
__device__ __forceinline__ float frcp(float x) {
    float r;
    asm("rcp.approx.f32 %0, %1;" : "=f"(r) : "f"(x));
    return r;
}
__device__ __forceinline__ float sigm(float x) {
    // 1/(1+e^-x); inf-safe with rcp.approx
    return frcp(1.0f + __expf(-x));
}
__device__ __forceinline__ float tanhfast(float x) {
    // 2/(1+e^-2x) - 1 ; inf-safe
    return fmaf(2.0f, frcp(1.0f + __expf(-2.0f * x)), -1.0f);
}

// ============================================================================
// Layer 0: input dim 1 (scalar x per step). Writes h-sequence to bufOut.
// ============================================================================
__global__ __launch_bounds__(128, 3) void lstm_layer0(
    const float* __restrict__ x,
    const float* __restrict__ wih,   // [128,1]
    const float* __restrict__ whh,   // [128,32]
    const float* __restrict__ bih,
    const float* __restrict__ bhh,
    float* __restrict__ bufOut)
{
    __shared__ float s_wih[4 * HID];
    __shared__ float s_b[4 * HID];
    __shared__ ull   s_whh[4 * HID * HID / 2];   // 128 rows x 16 pairs

    const int tid = threadIdx.x;
    for (int i = tid; i < 4 * HID; i += 128) {
        s_wih[i] = wih[i];
        s_b[i]   = bih[i] + bhh[i];
    }
    {
        float* sw = (float*)s_whh;
        for (int i = tid; i < 4 * HID * HID; i += 128) sw[i] = whh[i];
    }
    __syncthreads();

    const int seq = blockIdx.x * 128 + tid;
    const float* xs = x + (size_t)seq * TT;

    ull hp[16];
    float c[HID];
#pragma unroll
    for (int i = 0; i < 16; i++) hp[i] = 0ull;
#pragma unroll
    for (int i = 0; i < HID; i++) c[i] = 0.0f;

    for (int t = 0; t < TT; t++) {
        const float xt = __ldg(&xs[t]);
        ull hpn[16];
        float hprev = 0.0f;
#pragma unroll
        for (int j = 0; j < HID; j++) {
            const ull* whi = s_whh + (0 * HID + j) * 16;
            const ull* whf = s_whh + (1 * HID + j) * 16;
            const ull* whg = s_whh + (2 * HID + j) * 16;
            const ull* who = s_whh + (3 * HID + j) * 16;
            ull ai = 0, af = 0, ag = 0, ao = 0;
#pragma unroll
            for (int k = 0; k < 16; k++) {
                const ull hk = hp[k];
                ai = ffma2(whi[k], hk, ai);
                af = ffma2(whf[k], hk, af);
                ag = ffma2(whg[k], hk, ag);
                ao = ffma2(who[k], hk, ao);
            }
            float lo, hi, gi, gf, gg, go;
            unpack2(ai, lo, hi); gi = lo + hi + fmaf(xt, s_wih[0 * HID + j], s_b[0 * HID + j]);
            unpack2(af, lo, hi); gf = lo + hi + fmaf(xt, s_wih[1 * HID + j], s_b[1 * HID + j]);
            unpack2(ag, lo, hi); gg = lo + hi + fmaf(xt, s_wih[2 * HID + j], s_b[2 * HID + j]);
            unpack2(ao, lo, hi); go = lo + hi + fmaf(xt, s_wih[3 * HID + j], s_b[3 * HID + j]);

            const float I = sigm(gi);
            const float F = sigm(gf);
            const float G = tanhfast(gg);
            const float O = sigm(go);
            const float cj = fmaf(F, c[j], I * G);
            c[j] = cj;
            const float hj = O * tanhfast(cj);
            if (j & 1) hpn[j >> 1] = pack2(hprev, hj);
            else       hprev = hj;
        }
        ull* drow = (ull*)bufOut + ((size_t)t * NSEQ + seq) * (HID / 2);
#pragma unroll
        for (int i = 0; i < 16; i++) {
            drow[i] = hpn[i];
            hp[i] = hpn[i];
        }
    }
}

// ============================================================================
// Layers 1/2: input dim 32 (read from bufIn). FINAL fuses the FC head.
// ============================================================================
template <bool FINAL>
__global__ __launch_bounds__(128, 3) void lstm_layerN(
    const float* __restrict__ bufIn,
    float* __restrict__ bufOut,
    const float* __restrict__ wih,   // [128,32]
    const float* __restrict__ whh,   // [128,32]
    const float* __restrict__ bih,
    const float* __restrict__ bhh,
    const float* __restrict__ fcw,   // [1,32]
    const float* __restrict__ fcb,   // [1]
    float* __restrict__ out)
{
    __shared__ ull   s_wih[4 * HID * HID / 2];
    __shared__ ull   s_whh[4 * HID * HID / 2];
    __shared__ float s_b[4 * HID];
    __shared__ float s_fc[HID + 1];

    const int tid = threadIdx.x;
    {
        float* sw = (float*)s_wih;
        for (int i = tid; i < 4 * HID * HID; i += 128) sw[i] = wih[i];
        float* sh = (float*)s_whh;
        for (int i = tid; i < 4 * HID * HID; i += 128) sh[i] = whh[i];
    }
    for (int i = tid; i < 4 * HID; i += 128) s_b[i] = bih[i] + bhh[i];
    if (FINAL) {
        for (int i = tid; i < HID; i += 128) s_fc[i] = fcw[i];
        if (tid == 0) s_fc[HID] = fcb[0];
    }
    __syncthreads();

    const int seq = blockIdx.x * 128 + tid;

    ull hp[16];
    float c[HID];
#pragma unroll
    for (int i = 0; i < 16; i++) hp[i] = 0ull;
#pragma unroll
    for (int i = 0; i < HID; i++) c[i] = 0.0f;

    for (int t = 0; t < TT; t++) {
        const ull* __restrict__ xrow =
            (const ull*)bufIn + ((size_t)t * NSEQ + seq) * (HID / 2);
        ull xp[16];
#pragma unroll
        for (int i = 0; i < 16; i++) xp[i] = __ldg(&xrow[i]);

        ull hpn[16];
        float hprev = 0.0f;
#pragma unroll
        for (int j = 0; j < HID; j++) {
            const ull* wii = s_wih + (0 * HID + j) * 16;
            const ull* wif = s_wih + (1 * HID + j) * 16;
            const ull* wig = s_wih + (2 * HID + j) * 16;
            const ull* wio = s_wih + (3 * HID + j) * 16;
            const ull* whi = s_whh + (0 * HID + j) * 16;
            const ull* whf = s_whh + (1 * HID + j) * 16;
            const ull* whg = s_whh + (2 * HID + j) * 16;
            const ull* who = s_whh + (3 * HID + j) * 16;
            ull ai = 0, af = 0, ag = 0, ao = 0;
#pragma unroll
            for (int k = 0; k < 16; k++) {
                const ull hk = hp[k];
                const ull xk = xp[k];
                ai = ffma2(whi[k], hk, ai);
                af = ffma2(whf[k], hk, af);
                ag = ffma2(whg[k], hk, ag);
                ao = ffma2(who[k], hk, ao);
                ai = ffma2(wii[k], xk, ai);
                af = ffma2(wif[k], xk, af);
                ag = ffma2(wig[k], xk, ag);
                ao = ffma2(wio[k], xk, ao);
            }
            float lo, hi, gi, gf, gg, go;
            unpack2(ai, lo, hi); gi = lo + hi + s_b[0 * HID + j];
            unpack2(af, lo, hi); gf = lo + hi + s_b[1 * HID + j];
            unpack2(ag, lo, hi); gg = lo + hi + s_b[2 * HID + j];
            unpack2(ao, lo, hi); go = lo + hi + s_b[3 * HID + j];

            const float I = sigm(gi);
            const float F = sigm(gf);
            const float G = tanhfast(gg);
            const float O = sigm(go);
            const float cj = fmaf(F, c[j], I * G);
            c[j] = cj;
            const float hj = O * tanhfast(cj);
            if (j & 1) hpn[j >> 1] = pack2(hprev, hj);
            else       hprev = hj;
        }
        if (!FINAL) {
            ull* drow = (ull*)bufOut + ((size_t)t * NSEQ + seq) * (HID / 2);
#pragma unroll
            for (int i = 0; i < 16; i++) {
                drow[i] = hpn[i];
                hp[i] = hpn[i];
            }
        } else {
#pragma unroll
            for (int i = 0; i < 16; i++) hp[i] = hpn[i];
        }
    }

    if (FINAL) {
        float acc = s_fc[HID];
#pragma unroll
        for (int k = 0; k < 16; k++) {
            float lo, hi;
            unpack2(hp[k], lo, hi);
            acc = fmaf(lo, s_fc[2 * k + 0], acc);
            acc = fmaf(hi, s_fc[2 * k + 1], acc);
        }
        out[seq] = acc;
    }
}

// ============================================================================
extern "C" void kernel_launch(void* const* d_in, const int* in_sizes, int n_in,
                              void* d_out, int out_size)
{
    const float* x    = (const float*)d_in[0];
    const float* wih0 = (const float*)d_in[1];
    const float* whh0 = (const float*)d_in[2];
    const float* bih0 = (const float*)d_in[3];
    const float* bhh0 = (const float*)d_in[4];
    const float* wih1 = (const float*)d_in[5];
    const float* whh1 = (const float*)d_in[6];
    const float* bih1 = (const float*)d_in[7];
    const float* bhh1 = (const float*)d_in[8];
    const float* wih2 = (const float*)d_in[9];
    const float* whh2 = (const float*)d_in[10];
    const float* bih2 = (const float*)d_in[11];
    const float* bhh2 = (const float*)d_in[12];
    const float* fcw  = (const float*)d_in[13];
    const float* fcb  = (const float*)d_in[14];
    float* out = (float*)d_out;

    float* bufA = nullptr;
    float* bufB = nullptr;
    cudaGetSymbolAddress((void**)&bufA, g_bufA);
    cudaGetSymbolAddress((void**)&bufB, g_bufB);

    dim3 grid(NSEQ / 128), block(128);
    lstm_layer0<<<grid, block>>>(x, wih0, whh0, bih0, bhh0, bufA);
    lstm_layerN<false><<<grid, block>>>(bufA, bufB, wih1, whh1, bih1, bhh1,
                                        nullptr, nullptr, nullptr);
    lstm_layerN<true><<<grid, block>>>(bufB, nullptr, wih2, whh2, bih2, bhh2,
                                       fcw, fcb, out);
}

// round 11
// speedup vs baseline: 1.2291x; 1.2291x over previous
#include <cuda_runtime.h>

// ============================================================================
// 3-layer LSTM (H=32, T=64) over 65536 sequences + FC(32->1).
// TWO THREADS PER SEQUENCE (j-split halves). ONLY scalar 64-bit memory ops
// (LDS.64/LDG.64/STG.64 via plain C++ derefs) — every 128-bit access variant
// (ulonglong2, inline v2.u64) blew up local memory (>8KiB/thread guard).
// Activations via HW tanh.approx (1 MUFU) instead of exp+rcp (halves MUFU).
// ============================================================================

#define HID 32
#define TT 64
#define NSEQ 65536

typedef unsigned long long ull;

// scratch: [t][seq][32] floats, 512 MB (uninitialized .bss, no alloc)
__device__ float g_buf[(size_t)NSEQ * TT * HID];

// ---------------- packed f32x2 helpers (register-only asm) ----------------
__device__ __forceinline__ ull ffma2(ull a, ull b, ull c) {
    ull d;
    asm("fma.rn.f32x2 %0, %1, %2, %3;" : "=l"(d) : "l"(a), "l"(b), "l"(c));
    return d;
}
__device__ __forceinline__ ull pack2(float lo, float hi) {
    ull r;
    asm("mov.b64 %0, {%1, %2};" : "=l"(r) : "f"(lo), "f"(hi));
    return r;
}
__device__ __forceinline__ void unpack2(ull v, float& lo, float& hi) {
    asm("mov.b64 {%0, %1}, %2;" : "=f"(lo), "=f"(hi) : "l"(v));
}

// ---------------- fast activations (1 MUFU each) ----------------
__device__ __forceinline__ float tanha(float x) {
    float r;
    asm("tanh.approx.f32 %0, %1;" : "=f"(r) : "f"(x));
    return r;
}
__device__ __forceinline__ float sigm(float x) {
    return fmaf(0.5f, tanha(0.5f * x), 0.5f);
}

// h-exchange row stride in ull (padding vs bank conflicts; exchange is ~16
// ops/step vs ~2048 compute ops -> cost negligible either way)
#define HROW 18

// ============================================================================
// Layer 0: input dim 1. Block = 128 thr = 64 sequences (2 thr/seq).
// ============================================================================
__global__ __launch_bounds__(128, 3) void lstm_layer0(
    const float* __restrict__ x,
    const float* __restrict__ wih,   // [128,1]
    const float* __restrict__ whh,   // [128,32]
    const float* __restrict__ bih,
    const float* __restrict__ bhh,
    float* __restrict__ bufOut)
{
    __shared__ float s_wih[4 * HID];
    __shared__ float s_b[4 * HID];
    __shared__ ull   s_whh[4 * HID * HID / 2];  // 128 rows x 16 ull
    __shared__ ull   s_h[64 * HROW];

    const int tid = threadIdx.x;
    for (int i = tid; i < 4 * HID; i += 128) {
        s_wih[i] = wih[i];
        s_b[i]   = bih[i] + bhh[i];
    }
    {
        float* sw = (float*)s_whh;
        for (int i = tid; i < 4 * HID * HID; i += 128) sw[i] = whh[i];
    }
    __syncthreads();

    const int lane = tid & 31;
    const int wid  = tid >> 5;
    const int half = wid & 1;                 // 0: j 0..15, 1: j 16..31
    const int sIdx = (wid >> 1) * 32 + lane;  // seq within block, 0..63
    const int seq  = blockIdx.x * 64 + sIdx;
    const float* xs = x + (size_t)seq * TT;

    ull hp[16];
    float c[16];
#pragma unroll
    for (int i = 0; i < 16; i++) hp[i] = 0ull;
#pragma unroll
    for (int i = 0; i < 16; i++) c[i] = 0.0f;

    for (int t = 0; t < TT; t++) {
        const float xt = __ldg(&xs[t]);
        ull hpn[8];
        float hprev = 0.0f;
#pragma unroll
        for (int jj = 0; jj < 16; jj++) {
            const int j = half * 16 + jj;
            const ull* r0 = s_whh + j * 16;          // gate i row
            const ull* r1 = r0 + 512;                // gate f (+32 rows)
            const ull* r2 = r0 + 1024;               // gate g
            const ull* r3 = r0 + 1536;               // gate o
            ull ai = 0, af = 0, ag = 0, ao = 0;
#pragma unroll
            for (int k = 0; k < 16; k++) {
                const ull hk = hp[k];
                ai = ffma2(r0[k], hk, ai);
                af = ffma2(r1[k], hk, af);
                ag = ffma2(r2[k], hk, ag);
                ao = ffma2(r3[k], hk, ao);
            }
            float lo, hi, gi, gf, gg, go;
            unpack2(ai, lo, hi); gi = lo + hi + fmaf(xt, s_wih[0 * HID + j], s_b[0 * HID + j]);
            unpack2(af, lo, hi); gf = lo + hi + fmaf(xt, s_wih[1 * HID + j], s_b[1 * HID + j]);
            unpack2(ag, lo, hi); gg = lo + hi + fmaf(xt, s_wih[2 * HID + j], s_b[2 * HID + j]);
            unpack2(ao, lo, hi); go = lo + hi + fmaf(xt, s_wih[3 * HID + j], s_b[3 * HID + j]);

            const float I = sigm(gi);
            const float F = sigm(gf);
            const float G = tanha(gg);
            const float O = sigm(go);
            const float cj = fmaf(F, c[jj], I * G);
            c[jj] = cj;
            const float hj = O * tanha(cj);
            if (jj & 1) hpn[jj >> 1] = pack2(hprev, hj);
            else        hprev = hj;
        }
        // exchange h halves through SMEM (scalar 64-bit)
        ull* wrow = s_h + sIdx * HROW + half * 8;
#pragma unroll
        for (int p = 0; p < 8; p++) wrow[p] = hpn[p];
        __syncthreads();
        const ull* rrow = s_h + sIdx * HROW;
#pragma unroll
        for (int p = 0; p < 16; p++) hp[p] = rrow[p];
        __syncthreads();
        // store own half of h row (scalar 64-bit)
        ull* drow = (ull*)bufOut + ((size_t)t * NSEQ + seq) * (HID / 2) + half * 8;
#pragma unroll
        for (int p = 0; p < 8; p++) drow[p] = hpn[p];
    }
}

// ============================================================================
// Layers 1/2: input dim 32 from buf. Fused SMEM rows per (gate,unit):
// 32 ull = [16 ull whh | 16 ull wih]. In-place safe within a warp pair
// (both halves load xp before the mid-step syncs; write after).
// FINAL fuses the FC head (half-0 threads hold full h after last exchange).
// ============================================================================
template <bool FINAL>
__global__ __launch_bounds__(128, 3) void lstm_layerN(
    float* __restrict__ buf,
    const float* __restrict__ wih,   // [128,32]
    const float* __restrict__ whh,   // [128,32]
    const float* __restrict__ bih,
    const float* __restrict__ bhh,
    const float* __restrict__ fcw,   // [1,32]
    const float* __restrict__ fcb,   // [1]
    float* __restrict__ out)
{
    __shared__ ull   s_w[4 * HID * HID];   // 128 rows x 32 ull = 32 KB
    __shared__ float s_b[4 * HID];
    __shared__ float s_fc[HID + 1];
    __shared__ ull   s_h[64 * HROW];

    const int tid = threadIdx.x;
    {
        float* sw = (float*)s_w;
        // per row r (64 floats): [0..32) = whh row r, [32..64) = wih row r
        for (int i = tid; i < 4 * HID * HID * 2; i += 128) {
            int r = i >> 6, col = i & 63;
            sw[i] = (col < HID) ? whh[r * HID + col] : wih[r * HID + (col - HID)];
        }
    }
    for (int i = tid; i < 4 * HID; i += 128) s_b[i] = bih[i] + bhh[i];
    if (FINAL) {
        for (int i = tid; i < HID; i += 128) s_fc[i] = fcw[i];
        if (tid == 0) s_fc[HID] = fcb[0];
    }
    __syncthreads();

    const int lane = tid & 31;
    const int wid  = tid >> 5;
    const int half = wid & 1;
    const int sIdx = (wid >> 1) * 32 + lane;
    const int seq  = blockIdx.x * 64 + sIdx;

    ull hp[16];
    float c[16];
#pragma unroll
    for (int i = 0; i < 16; i++) hp[i] = 0ull;
#pragma unroll
    for (int i = 0; i < 16; i++) c[i] = 0.0f;

    for (int t = 0; t < TT; t++) {
        ull* xrow = (ull*)buf + ((size_t)t * NSEQ + seq) * (HID / 2);
        ull xp[16];
#pragma unroll
        for (int i = 0; i < 16; i++) xp[i] = __ldg(&xrow[i]);

        ull hpn[8];
        float hprev = 0.0f;
#pragma unroll
        for (int jj = 0; jj < 16; jj++) {
            const int j = half * 16 + jj;
            const ull* b0 = s_w + j * 32;            // gate i fused row
            const ull* b1 = b0 + 1024;               // gate f (+32 rows x 32)
            const ull* b2 = b0 + 2048;               // gate g
            const ull* b3 = b0 + 3072;               // gate o
            ull ai = 0, af = 0, ag = 0, ao = 0;
#pragma unroll
            for (int k = 0; k < 16; k++) {
                const ull hk = hp[k];
                const ull xk = xp[k];
                ai = ffma2(b0[k], hk, ai); ai = ffma2(b0[16 + k], xk, ai);
                af = ffma2(b1[k], hk, af); af = ffma2(b1[16 + k], xk, af);
                ag = ffma2(b2[k], hk, ag); ag = ffma2(b2[16 + k], xk, ag);
                ao = ffma2(b3[k], hk, ao); ao = ffma2(b3[16 + k], xk, ao);
            }
            float lo, hi, gi, gf, gg, go;
            unpack2(ai, lo, hi); gi = lo + hi + s_b[0 * HID + j];
            unpack2(af, lo, hi); gf = lo + hi + s_b[1 * HID + j];
            unpack2(ag, lo, hi); gg = lo + hi + s_b[2 * HID + j];
            unpack2(ao, lo, hi); go = lo + hi + s_b[3 * HID + j];

            const float I = sigm(gi);
            const float F = sigm(gf);
            const float G = tanha(gg);
            const float O = sigm(go);
            const float cj = fmaf(F, c[jj], I * G);
            c[jj] = cj;
            const float hj = O * tanha(cj);
            if (jj & 1) hpn[jj >> 1] = pack2(hprev, hj);
            else        hprev = hj;
        }
        // exchange h halves
        ull* wrow = s_h + sIdx * HROW + half * 8;
#pragma unroll
        for (int p = 0; p < 8; p++) wrow[p] = hpn[p];
        __syncthreads();
        const ull* rrow = s_h + sIdx * HROW;
#pragma unroll
        for (int p = 0; p < 16; p++) hp[p] = rrow[p];
        __syncthreads();

        if (!FINAL) {
            ull* drow = xrow + half * 8;
#pragma unroll
            for (int p = 0; p < 8; p++) drow[p] = hpn[p];  // in-place, own row
        }
    }

    if (FINAL && half == 0) {
        float acc = s_fc[HID];
#pragma unroll
        for (int k = 0; k < 16; k++) {
            float lo, hi;
            unpack2(hp[k], lo, hi);
            acc = fmaf(lo, s_fc[2 * k + 0], acc);
            acc = fmaf(hi, s_fc[2 * k + 1], acc);
        }
        out[seq] = acc;
    }
}

// ============================================================================
extern "C" void kernel_launch(void* const* d_in, const int* in_sizes, int n_in,
                              void* d_out, int out_size)
{
    const float* x    = (const float*)d_in[0];
    const float* wih0 = (const float*)d_in[1];
    const float* whh0 = (const float*)d_in[2];
    const float* bih0 = (const float*)d_in[3];
    const float* bhh0 = (const float*)d_in[4];
    const float* wih1 = (const float*)d_in[5];
    const float* whh1 = (const float*)d_in[6];
    const float* bih1 = (const float*)d_in[7];
    const float* bhh1 = (const float*)d_in[8];
    const float* wih2 = (const float*)d_in[9];
    const float* whh2 = (const float*)d_in[10];
    const float* bih2 = (const float*)d_in[11];
    const float* bhh2 = (const float*)d_in[12];
    const float* fcw  = (const float*)d_in[13];
    const float* fcb  = (const float*)d_in[14];
    float* out = (float*)d_out;

    float* buf = nullptr;
    cudaGetSymbolAddress((void**)&buf, g_buf);

    dim3 grid(NSEQ / 64), block(128);
    lstm_layer0<<<grid, block>>>(x, wih0, whh0, bih0, bhh0, buf);
    lstm_layerN<false><<<grid, block>>>(buf, wih1, whh1, bih1, bhh1,
                                        nullptr, nullptr, nullptr);
    lstm_layerN<true><<<grid, block>>>(buf, wih2, whh2, bih2, bhh2,
                                       fcw, fcb, out);
}

// round 12
// speedup vs baseline: 1.5401x; 1.2530x over previous
#include <cuda_runtime.h>

// ============================================================================
// 3-layer LSTM (H=32, T=64) over 65536 sequences + FC(32->1).
// TWO THREADS PER SEQUENCE (j-split halves). Scalar 64-bit memory ops ONLY
// (every 128-bit variant tripped an 8KiB/thread local-memory blowup).
// Scratch layout TRANSPOSED to [t][k2][seq]: warp-coalesced LDG/STG
// (2 lines per access instead of 32 -> 16x fewer L1tex wavefronts).
// Activations via HW tanh.approx.
// ============================================================================

#define HID 32
#define TT 64
#define NSEQ 65536

typedef unsigned long long ull;

// scratch: [t][k2][seq] ull pairs, 512 MB (uninitialized .bss, no alloc)
// slot(t,k2,s) = (t*16 + k2)*NSEQ + s
__device__ ull g_buf[(size_t)TT * (HID / 2) * NSEQ];

// ---------------- packed f32x2 helpers (register-only asm) ----------------
__device__ __forceinline__ ull ffma2(ull a, ull b, ull c) {
    ull d;
    asm("fma.rn.f32x2 %0, %1, %2, %3;" : "=l"(d) : "l"(a), "l"(b), "l"(c));
    return d;
}
__device__ __forceinline__ ull pack2(float lo, float hi) {
    ull r;
    asm("mov.b64 %0, {%1, %2};" : "=l"(r) : "f"(lo), "f"(hi));
    return r;
}
__device__ __forceinline__ void unpack2(ull v, float& lo, float& hi) {
    asm("mov.b64 {%0, %1}, %2;" : "=f"(lo), "=f"(hi) : "l"(v));
}

// ---------------- fast activations (1 MUFU each) ----------------
__device__ __forceinline__ float tanha(float x) {
    float r;
    asm("tanh.approx.f32 %0, %1;" : "=f"(r) : "f"(x));
    return r;
}
__device__ __forceinline__ float sigm(float x) {
    return fmaf(0.5f, tanha(0.5f * x), 0.5f);
}

#define HROW 18

// ============================================================================
// Layer 0: input dim 1. Block = 128 thr = 64 sequences (2 thr/seq).
// ============================================================================
__global__ __launch_bounds__(128, 3) void lstm_layer0(
    const float* __restrict__ x,
    const float* __restrict__ wih,   // [128,1]
    const float* __restrict__ whh,   // [128,32]
    const float* __restrict__ bih,
    const float* __restrict__ bhh,
    ull* __restrict__ bufOut)
{
    __shared__ float s_wih[4 * HID];
    __shared__ float s_b[4 * HID];
    __shared__ ull   s_whh[4 * HID * HID / 2];  // 128 rows x 16 ull
    __shared__ ull   s_h[64 * HROW];

    const int tid = threadIdx.x;
    for (int i = tid; i < 4 * HID; i += 128) {
        s_wih[i] = wih[i];
        s_b[i]   = bih[i] + bhh[i];
    }
    {
        float* sw = (float*)s_whh;
        for (int i = tid; i < 4 * HID * HID; i += 128) sw[i] = whh[i];
    }
    __syncthreads();

    const int lane = tid & 31;
    const int wid  = tid >> 5;
    const int half = wid & 1;                 // 0: j 0..15, 1: j 16..31
    const int sIdx = (wid >> 1) * 32 + lane;  // seq within block, 0..63
    const int seq  = blockIdx.x * 64 + sIdx;
    const float* xs = x + (size_t)seq * TT;

    ull hp[16];
    float c[16];
#pragma unroll
    for (int i = 0; i < 16; i++) hp[i] = 0ull;
#pragma unroll
    for (int i = 0; i < 16; i++) c[i] = 0.0f;

    for (int t = 0; t < TT; t++) {
        const float xt = __ldg(&xs[t]);
        ull hpn[8];
        float hprev = 0.0f;
#pragma unroll
        for (int jj = 0; jj < 16; jj++) {
            const int j = half * 16 + jj;
            const ull* r0 = s_whh + j * 16;          // gate i row
            const ull* r1 = r0 + 512;                // gate f
            const ull* r2 = r0 + 1024;               // gate g
            const ull* r3 = r0 + 1536;               // gate o
            ull ai = 0, af = 0, ag = 0, ao = 0;
#pragma unroll
            for (int k = 0; k < 16; k++) {
                const ull hk = hp[k];
                ai = ffma2(r0[k], hk, ai);
                af = ffma2(r1[k], hk, af);
                ag = ffma2(r2[k], hk, ag);
                ao = ffma2(r3[k], hk, ao);
            }
            float lo, hi, gi, gf, gg, go;
            unpack2(ai, lo, hi); gi = lo + hi + fmaf(xt, s_wih[0 * HID + j], s_b[0 * HID + j]);
            unpack2(af, lo, hi); gf = lo + hi + fmaf(xt, s_wih[1 * HID + j], s_b[1 * HID + j]);
            unpack2(ag, lo, hi); gg = lo + hi + fmaf(xt, s_wih[2 * HID + j], s_b[2 * HID + j]);
            unpack2(ao, lo, hi); go = lo + hi + fmaf(xt, s_wih[3 * HID + j], s_b[3 * HID + j]);

            const float I = sigm(gi);
            const float F = sigm(gf);
            const float G = tanha(gg);
            const float O = sigm(go);
            const float cj = fmaf(F, c[jj], I * G);
            c[jj] = cj;
            const float hj = O * tanha(cj);
            if (jj & 1) hpn[jj >> 1] = pack2(hprev, hj);
            else        hprev = hj;
        }
        // exchange h halves through SMEM
        ull* wrow = s_h + sIdx * HROW + half * 8;
#pragma unroll
        for (int p = 0; p < 8; p++) wrow[p] = hpn[p];
        __syncthreads();
        const ull* rrow = s_h + sIdx * HROW;
#pragma unroll
        for (int p = 0; p < 16; p++) hp[p] = rrow[p];
        __syncthreads();
        // store own half: transposed layout, lane-consecutive -> coalesced
#pragma unroll
        for (int p = 0; p < 8; p++)
            bufOut[(unsigned)(t * 16 + half * 8 + p) * NSEQ + seq] = hpn[p];
    }
}

// ============================================================================
// Layers 1/2: input dim 32 from transposed buf. Fused SMEM rows per
// (gate,unit): 32 ull = [16 ull whh | 16 ull wih]. In-place safe (reads of
// step t complete before this block's writes of step t; seq columns are
// block-disjoint). FINAL fuses the FC head.
// ============================================================================
template <bool FINAL>
__global__ __launch_bounds__(128, 3) void lstm_layerN(
    ull* __restrict__ buf,
    const float* __restrict__ wih,   // [128,32]
    const float* __restrict__ whh,   // [128,32]
    const float* __restrict__ bih,
    const float* __restrict__ bhh,
    const float* __restrict__ fcw,   // [1,32]
    const float* __restrict__ fcb,   // [1]
    float* __restrict__ out)
{
    __shared__ ull   s_w[4 * HID * HID];   // 128 rows x 32 ull = 32 KB
    __shared__ float s_b[4 * HID];
    __shared__ float s_fc[HID + 1];
    __shared__ ull   s_h[64 * HROW];

    const int tid = threadIdx.x;
    {
        float* sw = (float*)s_w;
        // per row r (64 floats): [0..32) = whh row r, [32..64) = wih row r
        for (int i = tid; i < 4 * HID * HID * 2; i += 128) {
            int r = i >> 6, col = i & 63;
            sw[i] = (col < HID) ? whh[r * HID + col] : wih[r * HID + (col - HID)];
        }
    }
    for (int i = tid; i < 4 * HID; i += 128) s_b[i] = bih[i] + bhh[i];
    if (FINAL) {
        for (int i = tid; i < HID; i += 128) s_fc[i] = fcw[i];
        if (tid == 0) s_fc[HID] = fcb[0];
    }
    __syncthreads();

    const int lane = tid & 31;
    const int wid  = tid >> 5;
    const int half = wid & 1;
    const int sIdx = (wid >> 1) * 32 + lane;
    const int seq  = blockIdx.x * 64 + sIdx;

    ull hp[16];
    float c[16];
#pragma unroll
    for (int i = 0; i < 16; i++) hp[i] = 0ull;
#pragma unroll
    for (int i = 0; i < 16; i++) c[i] = 0.0f;

    for (int t = 0; t < TT; t++) {
        // coalesced reads: lane-consecutive seq at each (t,k2)
        ull xp[16];
#pragma unroll
        for (int k = 0; k < 16; k++)
            xp[k] = __ldg(&buf[(unsigned)(t * 16 + k) * NSEQ + seq]);

        ull hpn[8];
        float hprev = 0.0f;
#pragma unroll
        for (int jj = 0; jj < 16; jj++) {
            const int j = half * 16 + jj;
            const ull* b0 = s_w + j * 32;            // gate i fused row
            const ull* b1 = b0 + 1024;               // gate f
            const ull* b2 = b0 + 2048;               // gate g
            const ull* b3 = b0 + 3072;               // gate o
            ull ai = 0, af = 0, ag = 0, ao = 0;
#pragma unroll
            for (int k = 0; k < 16; k++) {
                const ull hk = hp[k];
                const ull xk = xp[k];
                ai = ffma2(b0[k], hk, ai); ai = ffma2(b0[16 + k], xk, ai);
                af = ffma2(b1[k], hk, af); af = ffma2(b1[16 + k], xk, af);
                ag = ffma2(b2[k], hk, ag); ag = ffma2(b2[16 + k], xk, ag);
                ao = ffma2(b3[k], hk, ao); ao = ffma2(b3[16 + k], xk, ao);
            }
            float lo, hi, gi, gf, gg, go;
            unpack2(ai, lo, hi); gi = lo + hi + s_b[0 * HID + j];
            unpack2(af, lo, hi); gf = lo + hi + s_b[1 * HID + j];
            unpack2(ag, lo, hi); gg = lo + hi + s_b[2 * HID + j];
            unpack2(ao, lo, hi); go = lo + hi + s_b[3 * HID + j];

            const float I = sigm(gi);
            const float F = sigm(gf);
            const float G = tanha(gg);
            const float O = sigm(go);
            const float cj = fmaf(F, c[jj], I * G);
            c[jj] = cj;
            const float hj = O * tanha(cj);
            if (jj & 1) hpn[jj >> 1] = pack2(hprev, hj);
            else        hprev = hj;
        }
        // exchange h halves
        ull* wrow = s_h + sIdx * HROW + half * 8;
#pragma unroll
        for (int p = 0; p < 8; p++) wrow[p] = hpn[p];
        __syncthreads();
        const ull* rrow = s_h + sIdx * HROW;
#pragma unroll
        for (int p = 0; p < 16; p++) hp[p] = rrow[p];
        __syncthreads();

        if (!FINAL) {
            // in-place, coalesced
#pragma unroll
            for (int p = 0; p < 8; p++)
                buf[(unsigned)(t * 16 + half * 8 + p) * NSEQ + seq] = hpn[p];
        }
    }

    if (FINAL && half == 0) {
        float acc = s_fc[HID];
#pragma unroll
        for (int k = 0; k < 16; k++) {
            float lo, hi;
            unpack2(hp[k], lo, hi);
            acc = fmaf(lo, s_fc[2 * k + 0], acc);
            acc = fmaf(hi, s_fc[2 * k + 1], acc);
        }
        out[seq] = acc;
    }
}

// ============================================================================
extern "C" void kernel_launch(void* const* d_in, const int* in_sizes, int n_in,
                              void* d_out, int out_size)
{
    const float* x    = (const float*)d_in[0];
    const float* wih0 = (const float*)d_in[1];
    const float* whh0 = (const float*)d_in[2];
    const float* bih0 = (const float*)d_in[3];
    const float* bhh0 = (const float*)d_in[4];
    const float* wih1 = (const float*)d_in[5];
    const float* whh1 = (const float*)d_in[6];
    const float* bih1 = (const float*)d_in[7];
    const float* bhh1 = (const float*)d_in[8];
    const float* wih2 = (const float*)d_in[9];
    const float* whh2 = (const float*)d_in[10];
    const float* bih2 = (const float*)d_in[11];
    const float* bhh2 = (const float*)d_in[12];
    const float* fcw  = (const float*)d_in[13];
    const float* fcb  = (const float*)d_in[14];
    float* out = (float*)d_out;

    ull* buf = nullptr;
    cudaGetSymbolAddress((void**)&buf, g_buf);

    dim3 grid(NSEQ / 64), block(128);
    lstm_layer0<<<grid, block>>>(x, wih0, whh0, bih0, bhh0, buf);
    lstm_layerN<false><<<grid, block>>>(buf, wih1, whh1, bih1, bhh1,
                                        nullptr, nullptr, nullptr);
    lstm_layerN<true><<<grid, block>>>(buf, wih2, whh2, bih2, bhh2,
                                       fcw, fcb, out);
}

// round 13
// speedup vs baseline: 1.7348x; 1.1264x over previous
#include <cuda_runtime.h>

// ============================================================================
// 3-layer LSTM (H=32, T=64) over 65536 sequences + FC(32->1).
// TWO THREADS PER SEQUENCE (j-split halves). Scalar 64-bit memory ops ONLY.
// Scratch transposed [t][k2][seq] (coalesced). tanh.approx activations.
// THIS ROUND: __launch_bounds__(128,4) (regs<=128 -> 4 CTAs/SM, 16 warps)
// + hpn[] eliminated (h pairs written straight into the SMEM exchange row)
// to fit the 128-reg budget without hot-path spill.
// ============================================================================

#define HID 32
#define TT 64
#define NSEQ 65536

typedef unsigned long long ull;

// scratch: [t][k2][seq] ull pairs, 512 MB (uninitialized .bss, no alloc)
__device__ ull g_buf[(size_t)TT * (HID / 2) * NSEQ];

// ---------------- packed f32x2 helpers (register-only asm) ----------------
__device__ __forceinline__ ull ffma2(ull a, ull b, ull c) {
    ull d;
    asm("fma.rn.f32x2 %0, %1, %2, %3;" : "=l"(d) : "l"(a), "l"(b), "l"(c));
    return d;
}
__device__ __forceinline__ ull pack2(float lo, float hi) {
    ull r;
    asm("mov.b64 %0, {%1, %2};" : "=l"(r) : "f"(lo), "f"(hi));
    return r;
}
__device__ __forceinline__ void unpack2(ull v, float& lo, float& hi) {
    asm("mov.b64 {%0, %1}, %2;" : "=f"(lo), "=f"(hi) : "l"(v));
}

// ---------------- fast activations (1 MUFU each) ----------------
__device__ __forceinline__ float tanha(float x) {
    float r;
    asm("tanh.approx.f32 %0, %1;" : "=f"(r) : "f"(x));
    return r;
}
__device__ __forceinline__ float sigm(float x) {
    return fmaf(0.5f, tanha(0.5f * x), 0.5f);
}

#define HROW 18

// ============================================================================
// Layer 0: input dim 1. Block = 128 thr = 64 sequences (2 thr/seq).
// ============================================================================
__global__ __launch_bounds__(128, 4) void lstm_layer0(
    const float* __restrict__ x,
    const float* __restrict__ wih,   // [128,1]
    const float* __restrict__ whh,   // [128,32]
    const float* __restrict__ bih,
    const float* __restrict__ bhh,
    ull* __restrict__ bufOut)
{
    __shared__ float s_wih[4 * HID];
    __shared__ float s_b[4 * HID];
    __shared__ ull   s_whh[4 * HID * HID / 2];  // 128 rows x 16 ull
    __shared__ ull   s_h[64 * HROW];

    const int tid = threadIdx.x;
    for (int i = tid; i < 4 * HID; i += 128) {
        s_wih[i] = wih[i];
        s_b[i]   = bih[i] + bhh[i];
    }
    {
        float* sw = (float*)s_whh;
        for (int i = tid; i < 4 * HID * HID; i += 128) sw[i] = whh[i];
    }
    __syncthreads();

    const int lane = tid & 31;
    const int wid  = tid >> 5;
    const int half = wid & 1;
    const int sIdx = (wid >> 1) * 32 + lane;
    const int seq  = blockIdx.x * 64 + sIdx;
    const float* xs = x + (size_t)seq * TT;

    ull* const myrow = s_h + sIdx * HROW;      // exchange row for this seq

    ull hp[16];
    float c[16];
#pragma unroll
    for (int i = 0; i < 16; i++) hp[i] = 0ull;
#pragma unroll
    for (int i = 0; i < 16; i++) c[i] = 0.0f;

    for (int t = 0; t < TT; t++) {
        const float xt = __ldg(&xs[t]);
        float hprev = 0.0f;
#pragma unroll
        for (int jj = 0; jj < 16; jj++) {
            const int j = half * 16 + jj;
            const ull* r0 = s_whh + j * 16;
            const ull* r1 = r0 + 512;
            const ull* r2 = r0 + 1024;
            const ull* r3 = r0 + 1536;
            ull ai = 0, af = 0, ag = 0, ao = 0;
#pragma unroll
            for (int k = 0; k < 16; k++) {
                const ull hk = hp[k];
                ai = ffma2(r0[k], hk, ai);
                af = ffma2(r1[k], hk, af);
                ag = ffma2(r2[k], hk, ag);
                ao = ffma2(r3[k], hk, ao);
            }
            float lo, hi, gi, gf, gg, go;
            unpack2(ai, lo, hi); gi = lo + hi + fmaf(xt, s_wih[0 * HID + j], s_b[0 * HID + j]);
            unpack2(af, lo, hi); gf = lo + hi + fmaf(xt, s_wih[1 * HID + j], s_b[1 * HID + j]);
            unpack2(ag, lo, hi); gg = lo + hi + fmaf(xt, s_wih[2 * HID + j], s_b[2 * HID + j]);
            unpack2(ao, lo, hi); go = lo + hi + fmaf(xt, s_wih[3 * HID + j], s_b[3 * HID + j]);

            const float I = sigm(gi);
            const float F = sigm(gf);
            const float G = tanha(gg);
            const float O = sigm(go);
            const float cj = fmaf(F, c[jj], I * G);
            c[jj] = cj;
            const float hj = O * tanha(cj);
            if (jj & 1) myrow[half * 8 + (jj >> 1)] = pack2(hprev, hj);
            else        hprev = hj;
        }
        __syncthreads();
#pragma unroll
        for (int p = 0; p < 16; p++) hp[p] = myrow[p];
        __syncthreads();
        // coalesced store of own half (values now in hp)
#pragma unroll
        for (int p = 0; p < 8; p++)
            bufOut[(unsigned)(t * 16 + half * 8 + p) * NSEQ + seq] = hp[half * 8 + p];
    }
}

// ============================================================================
// Layers 1/2: input dim 32 from transposed buf, in-place. Fused SMEM rows:
// 32 ull = [16 ull whh | 16 ull wih] per (gate,unit). FINAL fuses FC head.
// ============================================================================
template <bool FINAL>
__global__ __launch_bounds__(128, 4) void lstm_layerN(
    ull* __restrict__ buf,
    const float* __restrict__ wih,
    const float* __restrict__ whh,
    const float* __restrict__ bih,
    const float* __restrict__ bhh,
    const float* __restrict__ fcw,
    const float* __restrict__ fcb,
    float* __restrict__ out)
{
    __shared__ ull   s_w[4 * HID * HID];   // 32 KB
    __shared__ float s_b[4 * HID];
    __shared__ float s_fc[HID + 1];
    __shared__ ull   s_h[64 * HROW];

    const int tid = threadIdx.x;
    {
        float* sw = (float*)s_w;
        for (int i = tid; i < 4 * HID * HID * 2; i += 128) {
            int r = i >> 6, col = i & 63;
            sw[i] = (col < HID) ? whh[r * HID + col] : wih[r * HID + (col - HID)];
        }
    }
    for (int i = tid; i < 4 * HID; i += 128) s_b[i] = bih[i] + bhh[i];
    if (FINAL) {
        for (int i = tid; i < HID; i += 128) s_fc[i] = fcw[i];
        if (tid == 0) s_fc[HID] = fcb[0];
    }
    __syncthreads();

    const int lane = tid & 31;
    const int wid  = tid >> 5;
    const int half = wid & 1;
    const int sIdx = (wid >> 1) * 32 + lane;
    const int seq  = blockIdx.x * 64 + sIdx;

    ull* const myrow = s_h + sIdx * HROW;

    ull hp[16];
    float c[16];
#pragma unroll
    for (int i = 0; i < 16; i++) hp[i] = 0ull;
#pragma unroll
    for (int i = 0; i < 16; i++) c[i] = 0.0f;

    for (int t = 0; t < TT; t++) {
        ull xp[16];
#pragma unroll
        for (int k = 0; k < 16; k++)
            xp[k] = __ldg(&buf[(unsigned)(t * 16 + k) * NSEQ + seq]);

        float hprev = 0.0f;
#pragma unroll
        for (int jj = 0; jj < 16; jj++) {
            const int j = half * 16 + jj;
            const ull* b0 = s_w + j * 32;
            const ull* b1 = b0 + 1024;
            const ull* b2 = b0 + 2048;
            const ull* b3 = b0 + 3072;
            ull ai = 0, af = 0, ag = 0, ao = 0;
#pragma unroll
            for (int k = 0; k < 16; k++) {
                const ull hk = hp[k];
                const ull xk = xp[k];
                ai = ffma2(b0[k], hk, ai); ai = ffma2(b0[16 + k], xk, ai);
                af = ffma2(b1[k], hk, af); af = ffma2(b1[16 + k], xk, af);
                ag = ffma2(b2[k], hk, ag); ag = ffma2(b2[16 + k], xk, ag);
                ao = ffma2(b3[k], hk, ao); ao = ffma2(b3[16 + k], xk, ao);
            }
            float lo, hi, gi, gf, gg, go;
            unpack2(ai, lo, hi); gi = lo + hi + s_b[0 * HID + j];
            unpack2(af, lo, hi); gf = lo + hi + s_b[1 * HID + j];
            unpack2(ag, lo, hi); gg = lo + hi + s_b[2 * HID + j];
            unpack2(ao, lo, hi); go = lo + hi + s_b[3 * HID + j];

            const float I = sigm(gi);
            const float F = sigm(gf);
            const float G = tanha(gg);
            const float O = sigm(go);
            const float cj = fmaf(F, c[jj], I * G);
            c[jj] = cj;
            const float hj = O * tanha(cj);
            if (jj & 1) myrow[half * 8 + (jj >> 1)] = pack2(hprev, hj);
            else        hprev = hj;
        }
        __syncthreads();
#pragma unroll
        for (int p = 0; p < 16; p++) hp[p] = myrow[p];
        __syncthreads();

        if (!FINAL) {
            // in-place, coalesced; values in hp after exchange
#pragma unroll
            for (int p = 0; p < 8; p++)
                buf[(unsigned)(t * 16 + half * 8 + p) * NSEQ + seq] = hp[half * 8 + p];
        }
    }

    if (FINAL && half == 0) {
        float acc = s_fc[HID];
#pragma unroll
        for (int k = 0; k < 16; k++) {
            float lo, hi;
            unpack2(hp[k], lo, hi);
            acc = fmaf(lo, s_fc[2 * k + 0], acc);
            acc = fmaf(hi, s_fc[2 * k + 1], acc);
        }
        out[seq] = acc;
    }
}

// ============================================================================
extern "C" void kernel_launch(void* const* d_in, const int* in_sizes, int n_in,
                              void* d_out, int out_size)
{
    const float* x    = (const float*)d_in[0];
    const float* wih0 = (const float*)d_in[1];
    const float* whh0 = (const float*)d_in[2];
    const float* bih0 = (const float*)d_in[3];
    const float* bhh0 = (const float*)d_in[4];
    const float* wih1 = (const float*)d_in[5];
    const float* whh1 = (const float*)d_in[6];
    const float* bih1 = (const float*)d_in[7];
    const float* bhh1 = (const float*)d_in[8];
    const float* wih2 = (const float*)d_in[9];
    const float* whh2 = (const float*)d_in[10];
    const float* bih2 = (const float*)d_in[11];
    const float* bhh2 = (const float*)d_in[12];
    const float* fcw  = (const float*)d_in[13];
    const float* fcb  = (const float*)d_in[14];
    float* out = (float*)d_out;

    ull* buf = nullptr;
    cudaGetSymbolAddress((void**)&buf, g_buf);

    dim3 grid(NSEQ / 64), block(128);
    lstm_layer0<<<grid, block>>>(x, wih0, whh0, bih0, bhh0, buf);
    lstm_layerN<false><<<grid, block>>>(buf, wih1, whh1, bih1, bhh1,
                                        nullptr, nullptr, nullptr);
    lstm_layerN<true><<<grid, block>>>(buf, wih2, whh2, bih2, bhh2,
                                       fcw, fcb, out);
}

// round 16
// speedup vs baseline: 1.8483x; 1.0654x over previous
#include <cuda_runtime.h>

// ============================================================================
// 3-layer LSTM (H=32, T=64) over 65536 sequences + FC(32->1).
// R16 = R15 with the >2GB host-shadow .bss link failure fixed by chunking
// the time axis: xg is computed/consumed in 4 chunks of TCH=16 steps, so the
// xg scratch is 512 MB (total device globals ~1.04 GB, link-safe).
// LSTM state (h,c) round-trips through small global buffers between chunks.
// xg-precompute + recurrent pass with 2 seqs/thread (1 weight LDS : 2 ffma2).
// Scalar 64-bit memory ops ONLY (128-bit variants trip the lmem guard).
// ============================================================================

#define HID 32
#define TT 64
#define TCH 16
#define NCH (TT / TCH)
#define NSEQ 65536

typedef unsigned long long ull;

// h scratch: [t][k2][seq] ull (512 MB)
__device__ ull g_buf[(size_t)TT * (HID / 2) * NSEQ];
// xg scratch for ONE chunk: [t_loc][gp][seq] ull (512 MB)
__device__ ull g_xg[(size_t)TCH * 64 * NSEQ];
// inter-chunk state: h pairs [p][seq] (8 MB), c [unit][seq] (8 MB)
__device__ ull   g_hs[(size_t)(HID / 2) * NSEQ];
__device__ float g_cs[(size_t)HID * NSEQ];

// ---------------- packed f32x2 helpers ----------------
__device__ __forceinline__ ull ffma2(ull a, ull b, ull c) {
    ull d;
    asm("fma.rn.f32x2 %0, %1, %2, %3;" : "=l"(d) : "l"(a), "l"(b), "l"(c));
    return d;
}
__device__ __forceinline__ ull pack2(float lo, float hi) {
    ull r;
    asm("mov.b64 %0, {%1, %2};" : "=l"(r) : "f"(lo), "f"(hi));
    return r;
}
__device__ __forceinline__ void unpack2(ull v, float& lo, float& hi) {
    asm("mov.b64 {%0, %1}, %2;" : "=f"(lo), "=f"(hi) : "l"(v));
}

// ---------------- fast activations ----------------
__device__ __forceinline__ float tanha(float x) {
    float r;
    asm("tanh.approx.f32 %0, %1;" : "=f"(r) : "f"(x));
    return r;
}
__device__ __forceinline__ float sigm(float x) {
    return fmaf(0.5f, tanha(0.5f * x), 0.5f);
}

#define HROW 18

// ============================================================================
// Layer 0 (unchanged, known-good): input dim 1, 2 thr/seq, 64 seqs/block.
// ============================================================================
__global__ __launch_bounds__(128, 4) void lstm_layer0(
    const float* __restrict__ x,
    const float* __restrict__ wih, const float* __restrict__ whh,
    const float* __restrict__ bih, const float* __restrict__ bhh,
    ull* __restrict__ bufOut)
{
    __shared__ float s_wih[4 * HID];
    __shared__ float s_b[4 * HID];
    __shared__ ull   s_whh[4 * HID * HID / 2];
    __shared__ ull   s_h[64 * HROW];

    const int tid = threadIdx.x;
    for (int i = tid; i < 4 * HID; i += 128) {
        s_wih[i] = wih[i];
        s_b[i]   = bih[i] + bhh[i];
    }
    {
        float* sw = (float*)s_whh;
        for (int i = tid; i < 4 * HID * HID; i += 128) sw[i] = whh[i];
    }
    __syncthreads();

    const int lane = tid & 31;
    const int wid  = tid >> 5;
    const int half = wid & 1;
    const int sIdx = (wid >> 1) * 32 + lane;
    const int seq  = blockIdx.x * 64 + sIdx;
    const float* xs = x + (size_t)seq * TT;

    ull* const myrow = s_h + sIdx * HROW;

    ull hp[16];
    float c[16];
#pragma unroll
    for (int i = 0; i < 16; i++) hp[i] = 0ull;
#pragma unroll
    for (int i = 0; i < 16; i++) c[i] = 0.0f;

    for (int t = 0; t < TT; t++) {
        const float xt = __ldg(&xs[t]);
        float hprev = 0.0f;
#pragma unroll
        for (int jj = 0; jj < 16; jj++) {
            const int j = half * 16 + jj;
            const ull* r0 = s_whh + j * 16;
            const ull* r1 = r0 + 512;
            const ull* r2 = r0 + 1024;
            const ull* r3 = r0 + 1536;
            ull ai = 0, af = 0, ag = 0, ao = 0;
#pragma unroll
            for (int k = 0; k < 16; k++) {
                const ull hk = hp[k];
                ai = ffma2(r0[k], hk, ai);
                af = ffma2(r1[k], hk, af);
                ag = ffma2(r2[k], hk, ag);
                ao = ffma2(r3[k], hk, ao);
            }
            float lo, hi, gi, gf, gg, go;
            unpack2(ai, lo, hi); gi = lo + hi + fmaf(xt, s_wih[0 * HID + j], s_b[0 * HID + j]);
            unpack2(af, lo, hi); gf = lo + hi + fmaf(xt, s_wih[1 * HID + j], s_b[1 * HID + j]);
            unpack2(ag, lo, hi); gg = lo + hi + fmaf(xt, s_wih[2 * HID + j], s_b[2 * HID + j]);
            unpack2(ao, lo, hi); go = lo + hi + fmaf(xt, s_wih[3 * HID + j], s_b[3 * HID + j]);

            const float I = sigm(gi);
            const float F = sigm(gf);
            const float G = tanha(gg);
            const float O = sigm(go);
            const float cj = fmaf(F, c[jj], I * G);
            c[jj] = cj;
            const float hj = O * tanha(cj);
            if (jj & 1) myrow[half * 8 + (jj >> 1)] = pack2(hprev, hj);
            else        hprev = hj;
        }
        __syncthreads();
#pragma unroll
        for (int p = 0; p < 16; p++) hp[p] = myrow[p];
        __syncthreads();
#pragma unroll
        for (int p = 0; p < 8; p++)
            bufOut[(unsigned)(t * 16 + half * 8 + p) * NSEQ + seq] = hp[half * 8 + p];
    }
}

// ============================================================================
// xg pass (one T-chunk): xg[t_loc][gp][seq] = W_ih @ h_prev(t0+t_loc) + b.
// grid = (NSEQ/128, TCH); thread handles 2 seqs x 16 units (2x LDS reuse).
// ============================================================================
__global__ __launch_bounds__(128, 4) void xg_pass(
    const ull* __restrict__ bufIn,
    const float* __restrict__ wih,
    const float* __restrict__ bih, const float* __restrict__ bhh,
    ull* __restrict__ xg, int t0)
{
    __shared__ ull   s_w[4 * HID * HID / 2];   // 16 KB
    __shared__ float s_b[4 * HID];

    const int tid = threadIdx.x;
    {
        float* sw = (float*)s_w;
        for (int i = tid; i < 4 * HID * HID; i += 128) sw[i] = wih[i];
    }
    for (int i = tid; i < 4 * HID; i += 128) s_b[i] = bih[i] + bhh[i];
    __syncthreads();

    const int half = tid >> 6;
    const int s    = tid & 63;
    const int seqA = blockIdx.x * 128 + s;
    const int seqB = seqA + 64;
    const int tl   = blockIdx.y;
    const int t    = t0 + tl;

    ull xpA[16], xpB[16];
#pragma unroll
    for (int k = 0; k < 16; k++) {
        xpA[k] = __ldg(&bufIn[(unsigned)(t * 16 + k) * NSEQ + seqA]);
        xpB[k] = __ldg(&bufIn[(unsigned)(t * 16 + k) * NSEQ + seqB]);
    }

#pragma unroll
    for (int jj = 0; jj < 16; jj += 2) {
        float gA[2][4], gB[2][4];
#pragma unroll
        for (int u = 0; u < 2; u++) {
            const int j = half * 16 + jj + u;
#pragma unroll
            for (int g = 0; g < 4; g++) {
                const ull* r = s_w + (g * HID + j) * 16;
                ull aA = 0, aB = 0;
#pragma unroll
                for (int k = 0; k < 16; k++) {
                    const ull w = r[k];
                    aA = ffma2(w, xpA[k], aA);
                    aB = ffma2(w, xpB[k], aB);
                }
                float lo, hi;
                const float b = s_b[g * HID + j];
                unpack2(aA, lo, hi); gA[u][g] = lo + hi + b;
                unpack2(aB, lo, hi); gB[u][g] = lo + hi + b;
            }
        }
        const int up = half * 8 + (jj >> 1);
#pragma unroll
        for (int g = 0; g < 4; g++) {
            const unsigned row = (unsigned)(tl * 64 + g * 16 + up) * NSEQ;
            xg[row + seqA] = pack2(gA[0][g], gA[1][g]);
            xg[row + seqB] = pack2(gB[0][g], gB[1][g]);
        }
    }
}

// ============================================================================
// Recurrent pass, one T-chunk: h-matvec only, 2 seqs/thread, j-split halves.
// SMEM 48 KB: s_w 16K + s_h[p][seq] 16K + s_c[unit][seq] 16K.
// State (h,c) restored from / saved to global between chunks.
// FINAL computes the FC head on the last chunk only.
// ============================================================================
template <bool FINAL>
__global__ __launch_bounds__(128, 4) void rec_pass(
    const ull* __restrict__ xg,
    const float* __restrict__ whh,
    ull* __restrict__ bufOut,
    const float* __restrict__ fcw,
    const float* __restrict__ fcb,
    float* __restrict__ out, int t0)
{
    __shared__ ull   s_w[4 * HID * HID / 2];   // 16384 B
    __shared__ ull   s_h[16 * 128];            // 16384 B, [p][seq]
    __shared__ float s_c[HID * 128];           // 16384 B, [unit][seq]

    const int tid = threadIdx.x;
    {
        float* sw = (float*)s_w;
        for (int i = tid; i < 4 * HID * HID; i += 128) sw[i] = whh[i];
    }
    const unsigned seq0 = blockIdx.x * 128;
    if (t0 == 0) {
        for (int i = tid; i < HID * 128; i += 128) s_c[i] = 0.0f;
    } else {
        for (int i = tid; i < HID * 128; i += 128) {
            const int unit = i >> 7, sl = i & 127;
            s_c[i] = g_cs[(unsigned)unit * NSEQ + seq0 + sl];
        }
    }
    __syncthreads();

    const int half = tid >> 6;
    const int s    = tid & 63;
    const int seqA = seq0 + s;
    const int seqB = seqA + 64;
    const int sA   = s;
    const int sB   = s + 64;

    ull hpA[16], hpB[16];
    if (t0 == 0) {
#pragma unroll
        for (int i = 0; i < 16; i++) { hpA[i] = 0ull; hpB[i] = 0ull; }
    } else {
#pragma unroll
        for (int p = 0; p < 16; p++) {
            hpA[p] = g_hs[(unsigned)p * NSEQ + seqA];
            hpB[p] = g_hs[(unsigned)p * NSEQ + seqB];
        }
    }

    for (int tl = 0; tl < TCH; tl++) {
        const int t = t0 + tl;
#pragma unroll
        for (int jj = 0; jj < 16; jj += 2) {
            const int up = half * 8 + (jj >> 1);
            ull xA[4], xB[4];
#pragma unroll
            for (int g = 0; g < 4; g++) {
                const unsigned row = (unsigned)(tl * 64 + g * 16 + up) * NSEQ;
                xA[g] = __ldg(&xg[row + seqA]);
                xB[g] = __ldg(&xg[row + seqB]);
            }
            float hEvenA = 0.0f, hEvenB = 0.0f;
#pragma unroll
            for (int u = 0; u < 2; u++) {
                const int j = half * 16 + jj + u;
                const ull* r0 = s_w + j * 16;
                const ull* r1 = r0 + 512;
                const ull* r2 = r0 + 1024;
                const ull* r3 = r0 + 1536;
                ull aiA = 0, afA = 0, agA = 0, aoA = 0;
                ull aiB = 0, afB = 0, agB = 0, aoB = 0;
#pragma unroll
                for (int k = 0; k < 16; k++) {
                    const ull hA = hpA[k], hB = hpB[k];
                    const ull w0 = r0[k];
                    aiA = ffma2(w0, hA, aiA); aiB = ffma2(w0, hB, aiB);
                    const ull w1 = r1[k];
                    afA = ffma2(w1, hA, afA); afB = ffma2(w1, hB, afB);
                    const ull w2 = r2[k];
                    agA = ffma2(w2, hA, agA); agB = ffma2(w2, hB, agB);
                    const ull w3 = r3[k];
                    aoA = ffma2(w3, hA, aoA); aoB = ffma2(w3, hB, aoB);
                }
                float lo, hi, e0, e1;
                unpack2(xA[0], e0, e1); unpack2(aiA, lo, hi);
                const float giA = lo + hi + (u ? e1 : e0);
                unpack2(xA[1], e0, e1); unpack2(afA, lo, hi);
                const float gfA = lo + hi + (u ? e1 : e0);
                unpack2(xA[2], e0, e1); unpack2(agA, lo, hi);
                const float ggA = lo + hi + (u ? e1 : e0);
                unpack2(xA[3], e0, e1); unpack2(aoA, lo, hi);
                const float goA = lo + hi + (u ? e1 : e0);
                unpack2(xB[0], e0, e1); unpack2(aiB, lo, hi);
                const float giB = lo + hi + (u ? e1 : e0);
                unpack2(xB[1], e0, e1); unpack2(afB, lo, hi);
                const float gfB = lo + hi + (u ? e1 : e0);
                unpack2(xB[2], e0, e1); unpack2(agB, lo, hi);
                const float ggB = lo + hi + (u ? e1 : e0);
                unpack2(xB[3], e0, e1); unpack2(aoB, lo, hi);
                const float goB = lo + hi + (u ? e1 : e0);

                float* cAp = s_c + j * 128 + sA;
                float* cBp = s_c + j * 128 + sB;
                const float cjA = fmaf(sigm(gfA), *cAp, sigm(giA) * tanha(ggA));
                const float cjB = fmaf(sigm(gfB), *cBp, sigm(giB) * tanha(ggB));
                *cAp = cjA;
                *cBp = cjB;
                const float hjA = sigm(goA) * tanha(cjA);
                const float hjB = sigm(goB) * tanha(cjB);
                if (u) {
                    s_h[up * 128 + sA] = pack2(hEvenA, hjA);
                    s_h[up * 128 + sB] = pack2(hEvenB, hjB);
                } else {
                    hEvenA = hjA;
                    hEvenB = hjB;
                }
            }
        }
        __syncthreads();
#pragma unroll
        for (int p = 0; p < 16; p++) {
            hpA[p] = s_h[p * 128 + sA];
            hpB[p] = s_h[p * 128 + sB];
        }
        __syncthreads();

        if (!FINAL) {
#pragma unroll
            for (int p = 0; p < 8; p++) {
                bufOut[(unsigned)(t * 16 + half * 8 + p) * NSEQ + seqA] = hpA[half * 8 + p];
                bufOut[(unsigned)(t * 16 + half * 8 + p) * NSEQ + seqB] = hpB[half * 8 + p];
            }
        }
    }

    // save state (s_c writes are fenced by the loop's trailing syncthreads)
    if (half == 0) {
#pragma unroll
        for (int p = 0; p < 16; p++) {
            g_hs[(unsigned)p * NSEQ + seqA] = hpA[p];
            g_hs[(unsigned)p * NSEQ + seqB] = hpB[p];
        }
    }
    for (int i = tid; i < HID * 128; i += 128) {
        const int unit = i >> 7, sl = i & 127;
        g_cs[(unsigned)unit * NSEQ + seq0 + sl] = s_c[i];
    }

    if (FINAL && (t0 + TCH == TT) && half == 0) {
        float accA = __ldg(&fcb[0]);
        float accB = accA;
#pragma unroll
        for (int k = 0; k < 16; k++) {
            const float w0 = __ldg(&fcw[2 * k]);
            const float w1 = __ldg(&fcw[2 * k + 1]);
            float lo, hi;
            unpack2(hpA[k], lo, hi);
            accA = fmaf(lo, w0, fmaf(hi, w1, accA));
            unpack2(hpB[k], lo, hi);
            accB = fmaf(lo, w0, fmaf(hi, w1, accB));
        }
        out[seqA] = accA;
        out[seqB] = accB;
    }
}

// ============================================================================
extern "C" void kernel_launch(void* const* d_in, const int* in_sizes, int n_in,
                              void* d_out, int out_size)
{
    const float* x    = (const float*)d_in[0];
    const float* wih0 = (const float*)d_in[1];
    const float* whh0 = (const float*)d_in[2];
    const float* bih0 = (const float*)d_in[3];
    const float* bhh0 = (const float*)d_in[4];
    const float* wih1 = (const float*)d_in[5];
    const float* whh1 = (const float*)d_in[6];
    const float* bih1 = (const float*)d_in[7];
    const float* bhh1 = (const float*)d_in[8];
    const float* wih2 = (const float*)d_in[9];
    const float* whh2 = (const float*)d_in[10];
    const float* bih2 = (const float*)d_in[11];
    const float* bhh2 = (const float*)d_in[12];
    const float* fcw  = (const float*)d_in[13];
    const float* fcb  = (const float*)d_in[14];
    float* out = (float*)d_out;

    ull* buf = nullptr;
    ull* xgb = nullptr;
    cudaGetSymbolAddress((void**)&buf, g_buf);
    cudaGetSymbolAddress((void**)&xgb, g_xg);

    dim3 blk(128);
    lstm_layer0<<<NSEQ / 64, blk>>>(x, wih0, whh0, bih0, bhh0, buf);

    dim3 gxg(NSEQ / 128, TCH);
    for (int c = 0; c < NCH; c++) {
        const int t0 = c * TCH;
        xg_pass<<<gxg, blk>>>(buf, wih1, bih1, bhh1, xgb, t0);
        rec_pass<false><<<NSEQ / 128, blk>>>(xgb, whh1, buf,
                                             nullptr, nullptr, nullptr, t0);
    }
    for (int c = 0; c < NCH; c++) {
        const int t0 = c * TCH;
        xg_pass<<<gxg, blk>>>(buf, wih2, bih2, bhh2, xgb, t0);
        rec_pass<true><<<NSEQ / 128, blk>>>(xgb, whh2, nullptr,
                                            fcw, fcb, out, t0);
    }
}